// round 9
// baseline (speedup 1.0000x reference)
#include <cuda_runtime.h>
#include <cuda_fp16.h>
#include <cstring>

// CombinedPriorityLoss: 0.1*MSE + 0.9*pairwise-rank + 0.1*diversity
// fp16x2 engine, 512x128 tiles (4 i-rows/thread -> 4x ILP, 1/4 LDS per pair),
// exact-weight triangle coverage, deterministic last-block finalize.

#define MARGIN 0.2f

constexpr int T = 128;             // threads per block == j-tile width
constexpr int MAXC = 128;          // max 128-col tiles (N <= 16384)
constexpr int MAXR = 32;           // max 512-row tiles
constexpr int MAXB = MAXR * MAXC;

__device__ float  g_partial[MAXB];   // combined A + 0.1*B per block
__device__ float  g_moms[MAXR][5];   // per 512-row granule
__device__ unsigned g_ticket = 0;

__device__ __forceinline__ __half2 u2h(unsigned u) {
    __half2 h; memcpy(&h, &u, 4); return h;
}
__device__ __forceinline__ unsigned h2u(__half2 h) {
    unsigned u; memcpy(&u, &h, 4); return u;
}

__global__ __launch_bounds__(T)
void fused_kernel(const float* __restrict__ pred,
                  const float* __restrict__ tgt,
                  int N, int nC, float* __restrict__ out) {
    const int bid = blockIdx.x;
    const int nblocks = gridDim.x;
    const int tid = threadIdx.x;
    const int lane = tid & 31;
    const int wid  = tid >> 5;
    const int nR = (nC + 3) >> 2;

    // decode (TI, tj): row TI covers tj in [4*TI, nC); cum(TI)=TI*nC-2*TI*(TI-1)
    int TI = 0;
    while ((TI + 1) * nC - 2 * (TI + 1) * TI <= bid) TI++;
    const int cum = TI * nC - 2 * TI * (TI - 1);
    const int tj = 4 * TI + (bid - cum);
    const int dd = tj - 4 * TI;

    // per-row weights: r<dd -> 1 ; r==dd -> 0.5 (both-ordered diag) ; r>dd -> 0
    float wr[4];
    #pragma unroll
    for (int r = 0; r < 4; r++)
        wr[r] = (r < dd) ? 1.f : ((r == dd) ? 0.5f : 0.f);

    __shared__ uint4 sP[T / 8];   // 128 x fp16(-0.1*pred[j])
    __shared__ uint4 sT[T / 8];   // 128 x fp16(-tgt[j])
    __shared__ float red[4][8];
    __shared__ int s_last;

    {
        int j = tj * T + tid;
        float pj = (j < N) ? pred[j] : 30000.f;   // finite pad -> 0 contribution
        float tv = (j < N) ? tgt[j]  : 30000.f;
        ((__half*)sP)[tid] = __float2half_rn(-0.1f * pj);
        ((__half*)sT)[tid] = __float2half_rn(-tv);
    }
    __syncthreads();

    const int ibase = TI * 512 + tid;
    float pf[4], tf[4];
    #pragma unroll
    for (int r = 0; r < 4; r++) {
        int i = ibase + r * 128;
        pf[r] = (i < N) ? pred[i] : 30000.f;
        tf[r] = (i < N) ? tgt[i]  : 30000.f;
    }

    float accC;
    {
        unsigned pi2[4], ti2[4];
        #pragma unroll
        for (int r = 0; r < 4; r++) {
            pi2[r] = h2u(__half2half2(__float2half_rn(0.1f * pf[r])));
            ti2[r] = h2u(__half2half2(__float2half_rn(tf[r])));
        }

        const __half2 M2   = __float2half2_rn(MARGIN);
        const __half2 Z2   = __float2half2_rn(0.f);
        const __half2 TEN2 = __float2half2_rn(10.f);

        __half2 acc[4][4];
        #pragma unroll
        for (int r = 0; r < 4; r++)
            #pragma unroll
            for (int q = 0; q < 4; q++) acc[r][q] = Z2;

        // per half2 (2 pairs): dp''=0.1(pi-pj), dt=ti-tj
        // qx''=(dt>0?-dp'':dp''), rv=max(10*qx''+M,0)
        // v = |dt|>M ? rv : |dp''|
        #define PAIR2(r, vpu, vtu, q) {                                       \
            unsigned dpu = h2u(__hadd2(u2h(pi2[r]), u2h(vpu)));               \
            unsigned dtu = h2u(__hadd2(u2h(ti2[r]), u2h(vtu)));               \
            unsigned qxu = dpu ^ 0x80008000u ^ (dtu & 0x80008000u);           \
            __half2 r2 = __hmax2(__hfma2(u2h(qxu), TEN2, M2), Z2);            \
            unsigned m = __hgt2_mask(u2h(dtu & 0x7FFF7FFFu), M2);             \
            unsigned vs = (h2u(r2) & m) | ((dpu & 0x7FFF7FFFu) & ~m);         \
            acc[r][q] = __hadd2(acc[r][q], u2h(vs)); }

        #pragma unroll 2
        for (int k = 0; k < T / 8; k++) {
            uint4 vp = sP[k];
            uint4 vt = sT[k];
            #pragma unroll
            for (int r = 0; r < 4; r++) {
                PAIR2(r, vp.x, vt.x, 0);
                PAIR2(r, vp.y, vt.y, 1);
                PAIR2(r, vp.z, vt.z, 2);
                PAIR2(r, vp.w, vt.w, 3);
            }
        }
        #undef PAIR2

        accC = 0.f;
        #pragma unroll
        for (int r = 0; r < 4; r++) {
            float c = 0.f;
            #pragma unroll
            for (int q = 0; q < 4; q++)
                c += __low2float(acc[r][q]) + __high2float(acc[r][q]);
            accC += c * wr[r];
        }
    }

    // block reduction (4 warps)
    #pragma unroll
    for (int o = 16; o; o >>= 1)
        accC += __shfl_down_sync(0xffffffffu, accC, o);
    if (lane == 0) red[wid][0] = accC;
    __syncthreads();
    if (tid == 0) {
        float a = 0.f;
        #pragma unroll
        for (int w2 = 0; w2 < 4; w2++) a += red[w2][0];
        g_partial[bid] = a;
    }
    __syncthreads();

    // dd==0 blocks: O(N) fp32 moments for this 512-row granule
    if (dd == 0) {
        float m[5] = {0.f, 0.f, 0.f, 0.f, 0.f};
        #pragma unroll
        for (int r = 0; r < 4; r++) {
            int i = ibase + r * 128;
            float p = (i < N) ? pf[r] : 0.f;
            float t = (i < N) ? tf[r] : 0.f;
            float d = p - t;
            m[0] += d * d; m[1] += p; m[2] += p * p; m[3] += t; m[4] += t * t;
        }
        #pragma unroll
        for (int k = 0; k < 5; k++) {
            float v = m[k];
            #pragma unroll
            for (int o = 16; o; o >>= 1) v += __shfl_down_sync(0xffffffffu, v, o);
            if (lane == 0) red[wid][k] = v;
        }
        __syncthreads();
        if (tid == 0) {
            #pragma unroll
            for (int k = 0; k < 5; k++) {
                float v = 0.f;
                #pragma unroll
                for (int w2 = 0; w2 < 4; w2++) v += red[w2][k];
                g_moms[TI][k] = v;
            }
        }
    }

    // ---- deterministic last-block finalize ----
    __threadfence();
    if (tid == 0) {
        unsigned t = atomicAdd(&g_ticket, 1u);
        s_last = (t == (unsigned)(nblocks - 1));
    }
    __syncthreads();
    if (!s_last) return;

    double aC = 0.0;
    for (int b = tid; b < nblocks; b += T) aC += (double)g_partial[b];
    double mm[5] = {0, 0, 0, 0, 0};
    for (int b = tid; b < nR; b += T) {
        #pragma unroll
        for (int k = 0; k < 5; k++) mm[k] += (double)g_moms[b][k];
    }

    __shared__ double dred[4][6];
    double vals[6] = { aC, mm[0], mm[1], mm[2], mm[3], mm[4] };
    #pragma unroll
    for (int k = 0; k < 6; k++) {
        double v = vals[k];
        #pragma unroll
        for (int o = 16; o; o >>= 1) v += __shfl_down_sync(0xffffffffu, v, o);
        if (lane == 0) dred[wid][k] = v;
    }
    __syncthreads();
    if (tid == 0) {
        double r[6];
        #pragma unroll
        for (int k = 0; k < 6; k++) {
            double v = 0.0;
            #pragma unroll
            for (int w2 = 0; w2 < 4; w2++) v += dred[w2][k];
            r[k] = v;
        }
        double n = (double)N;
        double mse = r[1] / n;
        double pred_var = (r[3] - r[2] * r[2] / n) / (n - 1.0);
        double tgt_var  = (r[5] - r[4] * r[4] / n) / (n - 1.0);
        double div = tgt_var - pred_var;
        if (div < 0.0) div = 0.0;
        long long pc = (long long)N * (N - 1) / 2;
        if (pc < 1) pc = 1;
        double rank = r[0] / (double)pc;   // coverage weight is exactly 1/pair
        out[0] = (float)(0.1 * mse + 0.9 * rank + 0.1 * div);
        g_ticket = 0;  // reset for graph replay
    }
}

extern "C" void kernel_launch(void* const* d_in, const int* in_sizes, int n_in,
                              void* d_out, int out_size) {
    const float* pred = (const float*)d_in[0];
    const float* tgt  = (const float*)d_in[1];
    float* out = (float*)d_out;
    int N = in_sizes[0];
    int nC = (N + T - 1) / T;          // 128-col tiles
    int nR = (nC + 3) / 4;             // 512-row tiles
    int nblocks = nR * nC - 2 * nR * (nR - 1);   // sum_{TI<nR} (nC - 4*TI)
    fused_kernel<<<nblocks, T>>>(pred, tgt, N, nC, out);
}